// round 1
// baseline (speedup 1.0000x reference)
#include <cuda_runtime.h>

static constexpr int NNODES = 100000;
static constexpr int NEDGES = 3200000;
static constexpr int NFEAT  = 512;
static constexpr int NHID   = 256;
static constexpr int SCAN_B = 1024;
static constexpr int NBLK_SCAN = (NNODES + SCAN_B - 1) / SCAN_B;  // 98

// ---- static device scratch (allocation-free per harness rules) ----
__device__ float g_support[NNODES * NHID];   // X@W1 result, reused for h1@W2
__device__ float g_h1[NNODES * NHID];        // layer-1 output
__device__ int   g_rowptr[NNODES + 1];
__device__ int   g_cursor[NNODES];
__device__ int   g_deg[NNODES];
__device__ int   g_bsum[128];
__device__ int   g_cols[NEDGES];
__device__ float g_vals[NEDGES];

// ============================ CSR construction ============================

__global__ void zero_deg_kernel() {
    int i = blockIdx.x * blockDim.x + threadIdx.x;
    if (i < NNODES) g_deg[i] = 0;
}

__global__ void count_deg_kernel(const int* __restrict__ erow) {
    int e = blockIdx.x * blockDim.x + threadIdx.x;
    if (e < NEDGES) atomicAdd(&g_deg[erow[e]], 1);
}

// chunk-local inclusive scan of degrees -> g_rowptr[gid+1]; chunk totals -> g_bsum
__global__ void scan1_kernel() {
    __shared__ int s[SCAN_B];
    int tx = threadIdx.x;
    int gid = blockIdx.x * SCAN_B + tx;
    int v = (gid < NNODES) ? g_deg[gid] : 0;
    s[tx] = v;
    __syncthreads();
    for (int off = 1; off < SCAN_B; off <<= 1) {
        int t = (tx >= off) ? s[tx - off] : 0;
        __syncthreads();
        s[tx] += t;
        __syncthreads();
    }
    if (gid < NNODES) g_rowptr[gid + 1] = s[tx];
    if (tx == SCAN_B - 1) g_bsum[blockIdx.x] = s[tx];
}

// inclusive scan of the 98 chunk totals
__global__ void scan2_kernel() {
    __shared__ int s[128];
    int tx = threadIdx.x;
    int v = (tx < NBLK_SCAN) ? g_bsum[tx] : 0;
    s[tx] = v;
    __syncthreads();
    for (int off = 1; off < 128; off <<= 1) {
        int t = (tx >= off) ? s[tx - off] : 0;
        __syncthreads();
        s[tx] += t;
        __syncthreads();
    }
    if (tx < NBLK_SCAN) g_bsum[tx] = s[tx];
}

// add chunk offsets; finalize rowptr and initialize cursor = rowptr[0..N-1]
__global__ void scan3_kernel() {
    int gid = blockIdx.x * SCAN_B + threadIdx.x;
    if (gid < NNODES) {
        int off = blockIdx.x ? g_bsum[blockIdx.x - 1] : 0;
        int v = g_rowptr[gid + 1] + off;
        g_rowptr[gid + 1] = v;
        if (gid + 1 < NNODES) g_cursor[gid + 1] = v;
        if (gid == 0) { g_rowptr[0] = 0; g_cursor[0] = 0; }
    }
}

__global__ void scatter_kernel(const int* __restrict__ erow,
                               const int* __restrict__ ecol,
                               const float* __restrict__ eval) {
    int e = blockIdx.x * blockDim.x + threadIdx.x;
    if (e < NEDGES) {
        int r = erow[e];
        int p = atomicAdd(&g_cursor[r], 1);
        g_cols[p] = ecol[e];
        g_vals[p] = eval[e];
    }
}

// ============================ fp32 SGEMM (128x128x8, 8x8/thread) ============================
// C[M,Nn] = A[M,K] @ B[K,Nn], all row-major. Nn and K multiples of 128 / 8; M guarded.

__global__ __launch_bounds__(256) void sgemm_kernel(
    int M, int Nn, int K,
    const float* __restrict__ A, const float* __restrict__ B, float* __restrict__ C)
{
    constexpr int BM = 128, BN = 128, BK = 8, TM = 8, TN = 8;
    __shared__ float As[BK][BM];
    __shared__ float Bs[BK][BN];

    int tid = threadIdx.x;
    int cRow = blockIdx.y, cCol = blockIdx.x;

    int threadCol = tid % (BN / TN);   // 0..15
    int threadRow = tid / (BN / TN);   // 0..15

    int innerRowA = tid / 2;           // 0..127
    int innerColA = (tid % 2) * 4;     // 0 or 4
    int innerRowB = tid / 32;          // 0..7
    int innerColB = (tid % 32) * 4;    // 0..124

    const float* Ab = A + (size_t)cRow * BM * K;
    const float* Bb = B + (size_t)cCol * BN;

    float acc[TM][TN];
#pragma unroll
    for (int i = 0; i < TM; i++)
#pragma unroll
        for (int j = 0; j < TN; j++) acc[i][j] = 0.f;

    float regM[TM], regN[TN];
    int aRow = cRow * BM + innerRowA;

    for (int k0 = 0; k0 < K; k0 += BK) {
        float4 av = make_float4(0.f, 0.f, 0.f, 0.f);
        if (aRow < M)
            av = *reinterpret_cast<const float4*>(Ab + (size_t)innerRowA * K + k0 + innerColA);
        As[innerColA + 0][innerRowA] = av.x;
        As[innerColA + 1][innerRowA] = av.y;
        As[innerColA + 2][innerRowA] = av.z;
        As[innerColA + 3][innerRowA] = av.w;

        float4 bv = *reinterpret_cast<const float4*>(Bb + (size_t)(k0 + innerRowB) * Nn + innerColB);
        *reinterpret_cast<float4*>(&Bs[innerRowB][innerColB]) = bv;
        __syncthreads();

#pragma unroll
        for (int kk = 0; kk < BK; kk++) {
#pragma unroll
            for (int i = 0; i < TM; i++) regM[i] = As[kk][threadRow * TM + i];
#pragma unroll
            for (int j = 0; j < TN; j++) regN[j] = Bs[kk][threadCol * TN + j];
#pragma unroll
            for (int i = 0; i < TM; i++)
#pragma unroll
                for (int j = 0; j < TN; j++) acc[i][j] += regM[i] * regN[j];
        }
        __syncthreads();
    }

#pragma unroll
    for (int i = 0; i < TM; i++) {
        int row = cRow * BM + threadRow * TM + i;
        if (row >= M) continue;
#pragma unroll
        for (int j = 0; j < TN; j += 4) {
            float4 v = make_float4(acc[i][j], acc[i][j + 1], acc[i][j + 2], acc[i][j + 3]);
            *reinterpret_cast<float4*>(C + (size_t)row * Nn + cCol * BN + threadCol * TN + j) = v;
        }
    }
}

// ============================ SpMM + bias + PReLU ============================
// out[r, :] = prelu( sum_{e in row r} val[e] * sup[col[e], :] + bias, alpha )
// 4 rows per block; 64 threads per row, float4 per thread (NHID=256).

__global__ __launch_bounds__(256) void spmm_bias_prelu_kernel(
    const float4* __restrict__ sup, const float* __restrict__ bias,
    const float* __restrict__ alpha, float4* __restrict__ out)
{
    int lane = threadIdx.x & 63;   // feature-chunk index (4 floats each)
    int rloc = threadIdx.x >> 6;   // 0..3
    int r = blockIdx.x * 4 + rloc;
    if (r >= NNODES) return;

    int s = g_rowptr[r];
    int e = g_rowptr[r + 1];
    float4 acc = make_float4(0.f, 0.f, 0.f, 0.f);
    for (int j = s; j < e; j++) {
        int c = g_cols[j];
        float v = g_vals[j];
        float4 x = sup[(size_t)c * 64 + lane];
        acc.x += v * x.x;
        acc.y += v * x.y;
        acc.z += v * x.z;
        acc.w += v * x.w;
    }
    float a = alpha[0];
    float4 b = reinterpret_cast<const float4*>(bias)[lane];
    float4 o;
    o.x = acc.x + b.x; o.x = o.x >= 0.f ? o.x : a * o.x;
    o.y = acc.y + b.y; o.y = o.y >= 0.f ? o.y : a * o.y;
    o.z = acc.z + b.z; o.z = o.z >= 0.f ? o.z : a * o.z;
    o.w = acc.w + b.w; o.w = o.w >= 0.f ? o.w : a * o.w;
    out[(size_t)r * 64 + lane] = o;
}

// ============================ launch ============================

extern "C" void kernel_launch(void* const* d_in, const int* in_sizes, int n_in,
                              void* d_out, int out_size) {
    const float* x     = (const float*)d_in[0];
    const int*   erow  = (const int*)  d_in[1];
    const int*   ecol  = (const int*)  d_in[2];
    const float* eval  = (const float*)d_in[3];
    const float* W1    = (const float*)d_in[4];
    const float* b1    = (const float*)d_in[5];
    const float* W2    = (const float*)d_in[6];
    const float* b2    = (const float*)d_in[7];
    const float* alpha = (const float*)d_in[8];
    float* out = (float*)d_out;

    float *sup = nullptr, *h1 = nullptr;
    cudaGetSymbolAddress((void**)&sup, g_support);
    cudaGetSymbolAddress((void**)&h1, g_h1);

    // CSR build (used by both SpMM layers)
    zero_deg_kernel<<<(NNODES + 255) / 256, 256>>>();
    count_deg_kernel<<<NEDGES / 256, 256>>>(erow);
    scan1_kernel<<<NBLK_SCAN, SCAN_B>>>();
    scan2_kernel<<<1, 128>>>();
    scan3_kernel<<<NBLK_SCAN, SCAN_B>>>();
    scatter_kernel<<<NEDGES / 256, 256>>>(erow, ecol, eval);

    dim3 gemm_grid(NHID / 128, (NNODES + 127) / 128);

    // Layer 1
    sgemm_kernel<<<gemm_grid, 256>>>(NNODES, NHID, NFEAT, x, W1, sup);
    spmm_bias_prelu_kernel<<<NNODES / 4, 256>>>((const float4*)sup, b1, alpha, (float4*)h1);

    // Layer 2
    sgemm_kernel<<<gemm_grid, 256>>>(NNODES, NHID, NHID, h1, W2, sup);
    spmm_bias_prelu_kernel<<<NNODES / 4, 256>>>((const float4*)sup, b2, alpha, (float4*)out);
}

// round 3
// speedup vs baseline: 1.4703x; 1.4703x over previous
#include <cuda_runtime.h>
#include <cuda_bf16.h>
#include <cstdint>

static constexpr int NNODES = 100000;
static constexpr int NEDGES = 3200000;
static constexpr int NFEAT  = 512;
static constexpr int NHID   = 256;
static constexpr int SCAN_B = 1024;
static constexpr int NBLK_SCAN = (NNODES + SCAN_B - 1) / SCAN_B;  // 98

// ---- static device scratch (allocation-free per harness rules) ----
__device__ float g_support[NNODES * NHID];
__device__ float g_h1[NNODES * NHID];
__device__ int   g_rowptr[NNODES + 1];
__device__ int   g_cursor[NNODES];
__device__ int   g_deg[NNODES];
__device__ int   g_bsum[128];
__device__ int   g_cols[NEDGES];
__device__ float g_vals[NEDGES];

// ============================ helpers ============================

__device__ __forceinline__ uint32_t smem_u32(const void* p) {
    uint32_t a;
    asm("{ .reg .u64 t; cvta.to.shared.u64 t, %1; cvt.u32.u64 %0, t; }"
        : "=r"(a) : "l"(p));
    return a;
}

// swizzle for 64-byte rows (8 rows x 64B atom): XOR bits[4:5] with bits[7:8]
__device__ __forceinline__ uint32_t sw64(uint32_t off) {
    return off ^ ((off >> 3) & 0x30);
}

__device__ __forceinline__ uint32_t pack_bf16x2(float a, float b) {
    __nv_bfloat162 t;
    t.x = __float2bfloat16(a);
    t.y = __float2bfloat16(b);
    return *reinterpret_cast<uint32_t*>(&t);
}

__device__ __forceinline__ void ldsm_x4(uint32_t* r, uint32_t addr) {
    asm volatile("ldmatrix.sync.aligned.m8n8.x4.shared.b16 {%0,%1,%2,%3}, [%4];"
        : "=r"(r[0]), "=r"(r[1]), "=r"(r[2]), "=r"(r[3]) : "r"(addr));
}

__device__ __forceinline__ void mma_bf16(float* c, const uint32_t* a,
                                         uint32_t b0, uint32_t b1) {
    asm volatile(
        "mma.sync.aligned.m16n8k16.row.col.f32.bf16.bf16.f32 "
        "{%0,%1,%2,%3}, {%4,%5,%6,%7}, {%8,%9}, {%0,%1,%2,%3};"
        : "+f"(c[0]), "+f"(c[1]), "+f"(c[2]), "+f"(c[3])
        : "r"(a[0]), "r"(a[1]), "r"(a[2]), "r"(a[3]), "r"(b0), "r"(b1));
}

// ============================ CSR construction ============================

__global__ void zero_deg_kernel() {
    int i = blockIdx.x * blockDim.x + threadIdx.x;
    if (i < NNODES) g_deg[i] = 0;
}

__global__ void count_deg_kernel(const int* __restrict__ erow) {
    int e = blockIdx.x * blockDim.x + threadIdx.x;
    if (e < NEDGES) atomicAdd(&g_deg[erow[e]], 1);
}

__global__ void scan1_kernel() {
    __shared__ int s[SCAN_B];
    int tx = threadIdx.x;
    int gid = blockIdx.x * SCAN_B + tx;
    int v = (gid < NNODES) ? g_deg[gid] : 0;
    s[tx] = v;
    __syncthreads();
    for (int off = 1; off < SCAN_B; off <<= 1) {
        int t = (tx >= off) ? s[tx - off] : 0;
        __syncthreads();
        s[tx] += t;
        __syncthreads();
    }
    if (gid < NNODES) g_rowptr[gid + 1] = s[tx];
    if (tx == SCAN_B - 1) g_bsum[blockIdx.x] = s[tx];
}

__global__ void scan2_kernel() {
    __shared__ int s[128];
    int tx = threadIdx.x;
    int v = (tx < NBLK_SCAN) ? g_bsum[tx] : 0;
    s[tx] = v;
    __syncthreads();
    for (int off = 1; off < 128; off <<= 1) {
        int t = (tx >= off) ? s[tx - off] : 0;
        __syncthreads();
        s[tx] += t;
        __syncthreads();
    }
    if (tx < NBLK_SCAN) g_bsum[tx] = s[tx];
}

__global__ void scan3_kernel() {
    int gid = blockIdx.x * SCAN_B + threadIdx.x;
    if (gid < NNODES) {
        int off = blockIdx.x ? g_bsum[blockIdx.x - 1] : 0;
        int v = g_rowptr[gid + 1] + off;
        g_rowptr[gid + 1] = v;
        if (gid + 1 < NNODES) g_cursor[gid + 1] = v;
        if (gid == 0) { g_rowptr[0] = 0; g_cursor[0] = 0; }
    }
}

__global__ void scatter_kernel(const int* __restrict__ erow,
                               const int* __restrict__ ecol,
                               const float* __restrict__ eval) {
    int e = blockIdx.x * blockDim.x + threadIdx.x;
    if (e < NEDGES) {
        int r = erow[e];
        int p = atomicAdd(&g_cursor[r], 1);
        g_cols[p] = ecol[e];
        g_vals[p] = eval[e];
    }
}

// ============================ bf16-split tensor-core GEMM ============================
// C[M,Nn] = A[M,K] @ B[K,Nn] (row-major fp32) via mma.sync bf16 hi/lo split:
//   C ~= Ah*Bh + Ah*Bl + Al*Bh  (fp32 accumulate)
// Block tile 128x128, BK=32, 256 threads (8 warps, each 32x64).

static constexpr int AH_OFF = 0;
static constexpr int AL_OFF = 8192;
static constexpr int BH_OFF = 16384;
static constexpr int BL_OFF = 24576;

__global__ __launch_bounds__(256) void gemm_mma_kernel(
    int M, int Nn, int K,
    const float* __restrict__ A, const float* __restrict__ B, float* __restrict__ C)
{
    __shared__ char smem[32768];
    uint32_t sb = smem_u32(smem);

    int tid = threadIdx.x;
    int lane = tid & 31;
    int wid = tid >> 5;
    int wm = wid & 3;          // warp row: 4 x 32 rows
    int wn = wid >> 2;         // warp col: 2 x 64 cols
    int m0 = blockIdx.y * 128;
    int n0 = blockIdx.x * 128;

    // staging coords
    int arow = tid & 127;               // A tile row
    int akh  = tid >> 7;                // which 16-k half
    int brow = tid & 127;               // B^T tile row (= n)
    int bkh  = tid >> 7;

    float aF[16], bF[16];
    float acc[2][8][4];
#pragma unroll
    for (int i = 0; i < 2; i++)
#pragma unroll
        for (int j = 0; j < 8; j++)
#pragma unroll
            for (int q = 0; q < 4; q++) acc[i][j][q] = 0.f;

    const int NC = K / 32;

    // ---- global load chunk into regs ----
    auto load_chunk = [&](int ch) {
        int k0 = ch * 32;
        int grow = m0 + arow;
        if (grow < M) {
            const float* ap = A + (size_t)grow * K + k0 + akh * 16;
#pragma unroll
            for (int g = 0; g < 4; g++) {
                float4 v = *reinterpret_cast<const float4*>(ap + g * 4);
                aF[g * 4 + 0] = v.x; aF[g * 4 + 1] = v.y;
                aF[g * 4 + 2] = v.z; aF[g * 4 + 3] = v.w;
            }
        } else {
#pragma unroll
            for (int j = 0; j < 16; j++) aF[j] = 0.f;
        }
        const float* bp = B + (size_t)(k0 + bkh * 16) * Nn + n0 + brow;
#pragma unroll
        for (int j = 0; j < 16; j++) bF[j] = bp[(size_t)j * Nn];
    };

    // ---- convert + store to SMEM ----
    auto store_chunk = [&]() {
        uint32_t hi[8], lo[8];
#pragma unroll
        for (int j = 0; j < 8; j++) {
            float x = aF[2 * j], y = aF[2 * j + 1];
            __nv_bfloat16 hx = __float2bfloat16(x);
            __nv_bfloat16 hy = __float2bfloat16(y);
            __nv_bfloat162 hp; hp.x = hx; hp.y = hy;
            hi[j] = *reinterpret_cast<uint32_t*>(&hp);
            lo[j] = pack_bf16x2(x - __bfloat162float(hx), y - __bfloat162float(hy));
        }
        uint32_t base = (uint32_t)(arow * 64 + akh * 32);
        *reinterpret_cast<uint4*>(smem + AH_OFF + sw64(base)) =
            make_uint4(hi[0], hi[1], hi[2], hi[3]);
        *reinterpret_cast<uint4*>(smem + AH_OFF + sw64(base + 16)) =
            make_uint4(hi[4], hi[5], hi[6], hi[7]);
        *reinterpret_cast<uint4*>(smem + AL_OFF + sw64(base)) =
            make_uint4(lo[0], lo[1], lo[2], lo[3]);
        *reinterpret_cast<uint4*>(smem + AL_OFF + sw64(base + 16)) =
            make_uint4(lo[4], lo[5], lo[6], lo[7]);

#pragma unroll
        for (int j = 0; j < 8; j++) {
            float x = bF[2 * j], y = bF[2 * j + 1];
            __nv_bfloat16 hx = __float2bfloat16(x);
            __nv_bfloat16 hy = __float2bfloat16(y);
            __nv_bfloat162 hp; hp.x = hx; hp.y = hy;
            hi[j] = *reinterpret_cast<uint32_t*>(&hp);
            lo[j] = pack_bf16x2(x - __bfloat162float(hx), y - __bfloat162float(hy));
        }
        base = (uint32_t)(brow * 64 + bkh * 32);
        *reinterpret_cast<uint4*>(smem + BH_OFF + sw64(base)) =
            make_uint4(hi[0], hi[1], hi[2], hi[3]);
        *reinterpret_cast<uint4*>(smem + BH_OFF + sw64(base + 16)) =
            make_uint4(hi[4], hi[5], hi[6], hi[7]);
        *reinterpret_cast<uint4*>(smem + BL_OFF + sw64(base)) =
            make_uint4(lo[0], lo[1], lo[2], lo[3]);
        *reinterpret_cast<uint4*>(smem + BL_OFF + sw64(base + 16)) =
            make_uint4(lo[4], lo[5], lo[6], lo[7]);
    };

    load_chunk(0);
    store_chunk();
    __syncthreads();

    for (int ch = 0; ; ch++) {
        bool last = (ch == NC - 1);
        if (!last) load_chunk(ch + 1);

        // ---- B fragments for whole chunk (both k-steps) ----
        uint32_t bh[8][4], bl[8][4];
        {
            uint32_t roff = (uint32_t)((wn * 64 + (lane & 7)) * 64 + (lane >> 3) * 16);
#pragma unroll
            for (int nt = 0; nt < 8; nt++) {
                uint32_t off = roff + (uint32_t)(nt * 8 * 64);
                ldsm_x4(bh[nt], sb + BH_OFF + sw64(off));
                ldsm_x4(bl[nt], sb + BL_OFF + sw64(off));
            }
        }

        // ---- k-steps ----
#pragma unroll
        for (int s = 0; s < 2; s++) {
            uint32_t ah[2][4], al[2][4];
            uint32_t roff = (uint32_t)((wm * 32 + (lane & 15)) * 64
                                       + s * 32 + (lane >> 4) * 16);
#pragma unroll
            for (int mt = 0; mt < 2; mt++) {
                uint32_t off = roff + (uint32_t)(mt * 16 * 64);
                ldsm_x4(ah[mt], sb + AH_OFF + sw64(off));
                ldsm_x4(al[mt], sb + AL_OFF + sw64(off));
            }
#pragma unroll
            for (int mt = 0; mt < 2; mt++)
#pragma unroll
                for (int nt = 0; nt < 8; nt++) {
                    mma_bf16(acc[mt][nt], ah[mt], bh[nt][2 * s], bh[nt][2 * s + 1]);
                    mma_bf16(acc[mt][nt], ah[mt], bl[nt][2 * s], bl[nt][2 * s + 1]);
                    mma_bf16(acc[mt][nt], al[mt], bh[nt][2 * s], bh[nt][2 * s + 1]);
                }
        }

        __syncthreads();
        if (last) break;
        store_chunk();
        __syncthreads();
    }

    // ---- epilogue ----
#pragma unroll
    for (int mt = 0; mt < 2; mt++) {
        int r0 = m0 + wm * 32 + mt * 16 + (lane >> 2);
        int r1 = r0 + 8;
#pragma unroll
        for (int nt = 0; nt < 8; nt++) {
            int c = n0 + wn * 64 + nt * 8 + (lane & 3) * 2;
            if (r0 < M)
                *reinterpret_cast<float2*>(C + (size_t)r0 * Nn + c) =
                    make_float2(acc[mt][nt][0], acc[mt][nt][1]);
            if (r1 < M)
                *reinterpret_cast<float2*>(C + (size_t)r1 * Nn + c) =
                    make_float2(acc[mt][nt][2], acc[mt][nt][3]);
        }
    }
}

// ============================ SpMM + bias + PReLU ============================

__global__ __launch_bounds__(256) void spmm_bias_prelu_kernel(
    const float4* __restrict__ sup, const float* __restrict__ bias,
    const float* __restrict__ alpha, float4* __restrict__ out)
{
    int lane = threadIdx.x & 63;
    int rloc = threadIdx.x >> 6;
    int r = blockIdx.x * 4 + rloc;
    if (r >= NNODES) return;

    int s = g_rowptr[r];
    int e = g_rowptr[r + 1];
    float4 acc = make_float4(0.f, 0.f, 0.f, 0.f);
    for (int j = s; j < e; j++) {
        int c = g_cols[j];
        float v = g_vals[j];
        float4 x = sup[(size_t)c * 64 + lane];
        acc.x += v * x.x;
        acc.y += v * x.y;
        acc.z += v * x.z;
        acc.w += v * x.w;
    }
    float a = alpha[0];
    float4 b = reinterpret_cast<const float4*>(bias)[lane];
    float4 o;
    o.x = acc.x + b.x; o.x = o.x >= 0.f ? o.x : a * o.x;
    o.y = acc.y + b.y; o.y = o.y >= 0.f ? o.y : a * o.y;
    o.z = acc.z + b.z; o.z = o.z >= 0.f ? o.z : a * o.z;
    o.w = acc.w + b.w; o.w = o.w >= 0.f ? o.w : a * o.w;
    out[(size_t)r * 64 + lane] = o;
}

// ============================ launch ============================

extern "C" void kernel_launch(void* const* d_in, const int* in_sizes, int n_in,
                              void* d_out, int out_size) {
    const float* x     = (const float*)d_in[0];
    const int*   erow  = (const int*)  d_in[1];
    const int*   ecol  = (const int*)  d_in[2];
    const float* eval  = (const float*)d_in[3];
    const float* W1    = (const float*)d_in[4];
    const float* b1    = (const float*)d_in[5];
    const float* W2    = (const float*)d_in[6];
    const float* b2    = (const float*)d_in[7];
    const float* alpha = (const float*)d_in[8];
    float* out = (float*)d_out;

    float *sup = nullptr, *h1 = nullptr;
    cudaGetSymbolAddress((void**)&sup, g_support);
    cudaGetSymbolAddress((void**)&h1, g_h1);

    // CSR build (used by both SpMM layers)
    zero_deg_kernel<<<(NNODES + 255) / 256, 256>>>();
    count_deg_kernel<<<NEDGES / 256, 256>>>(erow);
    scan1_kernel<<<NBLK_SCAN, SCAN_B>>>();
    scan2_kernel<<<1, 128>>>();
    scan3_kernel<<<NBLK_SCAN, SCAN_B>>>();
    scatter_kernel<<<NEDGES / 256, 256>>>(erow, ecol, eval);

    dim3 gemm_grid(NHID / 128, (NNODES + 127) / 128);

    // Layer 1
    gemm_mma_kernel<<<gemm_grid, 256>>>(NNODES, NHID, NFEAT, x, W1, sup);
    spmm_bias_prelu_kernel<<<NNODES / 4, 256>>>((const float4*)sup, b1, alpha, (float4*)h1);

    // Layer 2
    gemm_mma_kernel<<<gemm_grid, 256>>>(NNODES, NHID, NHID, h1, W2, sup);
    spmm_bias_prelu_kernel<<<NNODES / 4, 256>>>((const float4*)sup, b2, alpha, (float4*)out);
}

// round 4
// speedup vs baseline: 1.6720x; 1.1372x over previous
#include <cuda_runtime.h>
#include <cuda_bf16.h>
#include <cuda_fp16.h>
#include <cstdint>

static constexpr int NNODES = 100000;
static constexpr int NEDGES = 3200000;
static constexpr int NFEAT  = 512;
static constexpr int NHID   = 256;
static constexpr int SCAN_B = 1024;
static constexpr int NBLK_SCAN = (NNODES + SCAN_B - 1) / SCAN_B;  // 98

// ---- static device scratch (allocation-free per harness rules) ----
__device__ __half g_sup_h[NNODES * NHID];   // GEMM output in fp16 (gathered by SpMM)
__device__ float  g_h1[NNODES * NHID];      // layer-1 output (fp32, feeds GEMM2)
__device__ int    g_rowptr[NNODES + 1];
__device__ int    g_cursor[NNODES];
__device__ int    g_deg[NNODES];
__device__ int    g_bsum[128];
__device__ int    g_cols[NEDGES];
__device__ float  g_vals[NEDGES];

// ============================ helpers ============================

__device__ __forceinline__ uint32_t smem_u32(const void* p) {
    uint32_t a;
    asm("{ .reg .u64 t; cvta.to.shared.u64 t, %1; cvt.u32.u64 %0, t; }"
        : "=r"(a) : "l"(p));
    return a;
}

// swizzle for 64-byte rows (8 rows x 64B atom): XOR bits[4:5] with bits[7:8]
__device__ __forceinline__ uint32_t sw64(uint32_t off) {
    return off ^ ((off >> 3) & 0x30);
}

__device__ __forceinline__ uint32_t pack_bf16x2(float a, float b) {
    __nv_bfloat162 t;
    t.x = __float2bfloat16(a);
    t.y = __float2bfloat16(b);
    return *reinterpret_cast<uint32_t*>(&t);
}

__device__ __forceinline__ void ldsm_x4(uint32_t* r, uint32_t addr) {
    asm volatile("ldmatrix.sync.aligned.m8n8.x4.shared.b16 {%0,%1,%2,%3}, [%4];"
        : "=r"(r[0]), "=r"(r[1]), "=r"(r[2]), "=r"(r[3]) : "r"(addr));
}

__device__ __forceinline__ void mma_bf16(float* c, const uint32_t* a,
                                         uint32_t b0, uint32_t b1) {
    asm volatile(
        "mma.sync.aligned.m16n8k16.row.col.f32.bf16.bf16.f32 "
        "{%0,%1,%2,%3}, {%4,%5,%6,%7}, {%8,%9}, {%0,%1,%2,%3};"
        : "+f"(c[0]), "+f"(c[1]), "+f"(c[2]), "+f"(c[3])
        : "r"(a[0]), "r"(a[1]), "r"(a[2]), "r"(a[3]), "r"(b0), "r"(b1));
}

// ============================ CSR construction ============================

__global__ void zero_deg_kernel() {
    int i = blockIdx.x * blockDim.x + threadIdx.x;
    if (i < NNODES) g_deg[i] = 0;
}

__global__ void count_deg_kernel(const int* __restrict__ erow) {
    int e = blockIdx.x * blockDim.x + threadIdx.x;
    if (e < NEDGES) atomicAdd(&g_deg[erow[e]], 1);
}

__global__ void scan1_kernel() {
    __shared__ int s[SCAN_B];
    int tx = threadIdx.x;
    int gid = blockIdx.x * SCAN_B + tx;
    int v = (gid < NNODES) ? g_deg[gid] : 0;
    s[tx] = v;
    __syncthreads();
    for (int off = 1; off < SCAN_B; off <<= 1) {
        int t = (tx >= off) ? s[tx - off] : 0;
        __syncthreads();
        s[tx] += t;
        __syncthreads();
    }
    if (gid < NNODES) g_rowptr[gid + 1] = s[tx];
    if (tx == SCAN_B - 1) g_bsum[blockIdx.x] = s[tx];
}

__global__ void scan2_kernel() {
    __shared__ int s[128];
    int tx = threadIdx.x;
    int v = (tx < NBLK_SCAN) ? g_bsum[tx] : 0;
    s[tx] = v;
    __syncthreads();
    for (int off = 1; off < 128; off <<= 1) {
        int t = (tx >= off) ? s[tx - off] : 0;
        __syncthreads();
        s[tx] += t;
        __syncthreads();
    }
    if (tx < NBLK_SCAN) g_bsum[tx] = s[tx];
}

__global__ void scan3_kernel() {
    int gid = blockIdx.x * SCAN_B + threadIdx.x;
    if (gid < NNODES) {
        int off = blockIdx.x ? g_bsum[blockIdx.x - 1] : 0;
        int v = g_rowptr[gid + 1] + off;
        g_rowptr[gid + 1] = v;
        if (gid + 1 < NNODES) g_cursor[gid + 1] = v;
        if (gid == 0) { g_rowptr[0] = 0; g_cursor[0] = 0; }
    }
}

__global__ void scatter_kernel(const int* __restrict__ erow,
                               const int* __restrict__ ecol,
                               const float* __restrict__ eval) {
    int e = blockIdx.x * blockDim.x + threadIdx.x;
    if (e < NEDGES) {
        int r = erow[e];
        int p = atomicAdd(&g_cursor[r], 1);
        g_cols[p] = ecol[e];
        g_vals[p] = eval[e];
    }
}

// ============================ bf16-split tensor-core GEMM ============================
// Ch[M,Nn] = fp16( A[M,K] @ B[K,Nn] )  via mma.sync bf16 hi/lo split:
//   C ~= Ah*Bh + Ah*Bl + Al*Bh  (fp32 accumulate), epilogue rounds to fp16.
// Block tile 128x128, BK=32, 256 threads (8 warps, each 32x64).

static constexpr int AH_OFF = 0;
static constexpr int AL_OFF = 8192;
static constexpr int BH_OFF = 16384;
static constexpr int BL_OFF = 24576;

__global__ __launch_bounds__(256) void gemm_mma_kernel(
    int M, int Nn, int K,
    const float* __restrict__ A, const float* __restrict__ B, __half* __restrict__ Ch)
{
    __shared__ char smem[32768];
    uint32_t sb = smem_u32(smem);

    int tid = threadIdx.x;
    int lane = tid & 31;
    int wid = tid >> 5;
    int wm = wid & 3;          // warp row: 4 x 32 rows
    int wn = wid >> 2;         // warp col: 2 x 64 cols
    int m0 = blockIdx.y * 128;
    int n0 = blockIdx.x * 128;

    int arow = tid & 127;
    int akh  = tid >> 7;
    int brow = tid & 127;
    int bkh  = tid >> 7;

    float aF[16], bF[16];
    float acc[2][8][4];
#pragma unroll
    for (int i = 0; i < 2; i++)
#pragma unroll
        for (int j = 0; j < 8; j++)
#pragma unroll
            for (int q = 0; q < 4; q++) acc[i][j][q] = 0.f;

    const int NC = K / 32;

    auto load_chunk = [&](int ch) {
        int k0 = ch * 32;
        int grow = m0 + arow;
        if (grow < M) {
            const float* ap = A + (size_t)grow * K + k0 + akh * 16;
#pragma unroll
            for (int g = 0; g < 4; g++) {
                float4 v = *reinterpret_cast<const float4*>(ap + g * 4);
                aF[g * 4 + 0] = v.x; aF[g * 4 + 1] = v.y;
                aF[g * 4 + 2] = v.z; aF[g * 4 + 3] = v.w;
            }
        } else {
#pragma unroll
            for (int j = 0; j < 16; j++) aF[j] = 0.f;
        }
        const float* bp = B + (size_t)(k0 + bkh * 16) * Nn + n0 + brow;
#pragma unroll
        for (int j = 0; j < 16; j++) bF[j] = bp[(size_t)j * Nn];
    };

    auto store_chunk = [&]() {
        uint32_t hi[8], lo[8];
#pragma unroll
        for (int j = 0; j < 8; j++) {
            float x = aF[2 * j], y = aF[2 * j + 1];
            __nv_bfloat16 hx = __float2bfloat16(x);
            __nv_bfloat16 hy = __float2bfloat16(y);
            __nv_bfloat162 hp; hp.x = hx; hp.y = hy;
            hi[j] = *reinterpret_cast<uint32_t*>(&hp);
            lo[j] = pack_bf16x2(x - __bfloat162float(hx), y - __bfloat162float(hy));
        }
        uint32_t base = (uint32_t)(arow * 64 + akh * 32);
        *reinterpret_cast<uint4*>(smem + AH_OFF + sw64(base)) =
            make_uint4(hi[0], hi[1], hi[2], hi[3]);
        *reinterpret_cast<uint4*>(smem + AH_OFF + sw64(base + 16)) =
            make_uint4(hi[4], hi[5], hi[6], hi[7]);
        *reinterpret_cast<uint4*>(smem + AL_OFF + sw64(base)) =
            make_uint4(lo[0], lo[1], lo[2], lo[3]);
        *reinterpret_cast<uint4*>(smem + AL_OFF + sw64(base + 16)) =
            make_uint4(lo[4], lo[5], lo[6], lo[7]);

#pragma unroll
        for (int j = 0; j < 8; j++) {
            float x = bF[2 * j], y = bF[2 * j + 1];
            __nv_bfloat16 hx = __float2bfloat16(x);
            __nv_bfloat16 hy = __float2bfloat16(y);
            __nv_bfloat162 hp; hp.x = hx; hp.y = hy;
            hi[j] = *reinterpret_cast<uint32_t*>(&hp);
            lo[j] = pack_bf16x2(x - __bfloat162float(hx), y - __bfloat162float(hy));
        }
        base = (uint32_t)(brow * 64 + bkh * 32);
        *reinterpret_cast<uint4*>(smem + BH_OFF + sw64(base)) =
            make_uint4(hi[0], hi[1], hi[2], hi[3]);
        *reinterpret_cast<uint4*>(smem + BH_OFF + sw64(base + 16)) =
            make_uint4(hi[4], hi[5], hi[6], hi[7]);
        *reinterpret_cast<uint4*>(smem + BL_OFF + sw64(base)) =
            make_uint4(lo[0], lo[1], lo[2], lo[3]);
        *reinterpret_cast<uint4*>(smem + BL_OFF + sw64(base + 16)) =
            make_uint4(lo[4], lo[5], lo[6], lo[7]);
    };

    load_chunk(0);
    store_chunk();
    __syncthreads();

    for (int ch = 0; ; ch++) {
        bool last = (ch == NC - 1);
        if (!last) load_chunk(ch + 1);

        uint32_t bh[8][4], bl[8][4];
        {
            uint32_t roff = (uint32_t)((wn * 64 + (lane & 7)) * 64 + (lane >> 3) * 16);
#pragma unroll
            for (int nt = 0; nt < 8; nt++) {
                uint32_t off = roff + (uint32_t)(nt * 8 * 64);
                ldsm_x4(bh[nt], sb + BH_OFF + sw64(off));
                ldsm_x4(bl[nt], sb + BL_OFF + sw64(off));
            }
        }

#pragma unroll
        for (int s = 0; s < 2; s++) {
            uint32_t ah[2][4], al[2][4];
            uint32_t roff = (uint32_t)((wm * 32 + (lane & 15)) * 64
                                       + s * 32 + (lane >> 4) * 16);
#pragma unroll
            for (int mt = 0; mt < 2; mt++) {
                uint32_t off = roff + (uint32_t)(mt * 16 * 64);
                ldsm_x4(ah[mt], sb + AH_OFF + sw64(off));
                ldsm_x4(al[mt], sb + AL_OFF + sw64(off));
            }
#pragma unroll
            for (int mt = 0; mt < 2; mt++)
#pragma unroll
                for (int nt = 0; nt < 8; nt++) {
                    mma_bf16(acc[mt][nt], ah[mt], bh[nt][2 * s], bh[nt][2 * s + 1]);
                    mma_bf16(acc[mt][nt], ah[mt], bl[nt][2 * s], bl[nt][2 * s + 1]);
                    mma_bf16(acc[mt][nt], al[mt], bh[nt][2 * s], bh[nt][2 * s + 1]);
                }
        }

        __syncthreads();
        if (last) break;
        store_chunk();
        __syncthreads();
    }

    // ---- epilogue: fp32 acc -> fp16 support ----
#pragma unroll
    for (int mt = 0; mt < 2; mt++) {
        int r0 = m0 + wm * 32 + mt * 16 + (lane >> 2);
        int r1 = r0 + 8;
#pragma unroll
        for (int nt = 0; nt < 8; nt++) {
            int c = n0 + wn * 64 + nt * 8 + (lane & 3) * 2;
            if (r0 < M)
                *reinterpret_cast<__half2*>(Ch + (size_t)r0 * Nn + c) =
                    __floats2half2_rn(acc[mt][nt][0], acc[mt][nt][1]);
            if (r1 < M)
                *reinterpret_cast<__half2*>(Ch + (size_t)r1 * Nn + c) =
                    __floats2half2_rn(acc[mt][nt][2], acc[mt][nt][3]);
        }
    }
}

// ============================ SpMM (fp16 gather) + bias + PReLU ============================
// out[r, :] = prelu( sum_e val[e] * sup_h[col[e], :] + bias, alpha )
// 4 rows/block; 64 threads/row, 4 features (8 bytes fp16) per thread.

__global__ __launch_bounds__(256) void spmm_bias_prelu_kernel(
    const uint2* __restrict__ sup, const float* __restrict__ bias,
    const float* __restrict__ alpha, float4* __restrict__ out)
{
    int lane = threadIdx.x & 63;   // feature chunk: 4 halves
    int rloc = threadIdx.x >> 6;
    int r = blockIdx.x * 4 + rloc;
    if (r >= NNODES) return;

    int s = g_rowptr[r];
    int e = g_rowptr[r + 1];
    float4 acc = make_float4(0.f, 0.f, 0.f, 0.f);

    int j = s;
    for (; j + 1 < e; j += 2) {
        int   c0 = g_cols[j],     c1 = g_cols[j + 1];
        float v0 = g_vals[j],     v1 = g_vals[j + 1];
        uint2 p0 = sup[(size_t)c0 * 64 + lane];
        uint2 p1 = sup[(size_t)c1 * 64 + lane];
        float2 a0 = __half22float2(*reinterpret_cast<__half2*>(&p0.x));
        float2 b0 = __half22float2(*reinterpret_cast<__half2*>(&p0.y));
        float2 a1 = __half22float2(*reinterpret_cast<__half2*>(&p1.x));
        float2 b1 = __half22float2(*reinterpret_cast<__half2*>(&p1.y));
        acc.x += v0 * a0.x + v1 * a1.x;
        acc.y += v0 * a0.y + v1 * a1.y;
        acc.z += v0 * b0.x + v1 * b1.x;
        acc.w += v0 * b0.y + v1 * b1.y;
    }
    if (j < e) {
        int   c0 = g_cols[j];
        float v0 = g_vals[j];
        uint2 p0 = sup[(size_t)c0 * 64 + lane];
        float2 a0 = __half22float2(*reinterpret_cast<__half2*>(&p0.x));
        float2 b0 = __half22float2(*reinterpret_cast<__half2*>(&p0.y));
        acc.x += v0 * a0.x;
        acc.y += v0 * a0.y;
        acc.z += v0 * b0.x;
        acc.w += v0 * b0.y;
    }

    float a = alpha[0];
    float4 b = reinterpret_cast<const float4*>(bias)[lane];
    float4 o;
    o.x = acc.x + b.x; o.x = o.x >= 0.f ? o.x : a * o.x;
    o.y = acc.y + b.y; o.y = o.y >= 0.f ? o.y : a * o.y;
    o.z = acc.z + b.z; o.z = o.z >= 0.f ? o.z : a * o.z;
    o.w = acc.w + b.w; o.w = o.w >= 0.f ? o.w : a * o.w;
    out[(size_t)r * 64 + lane] = o;
}

// ============================ launch ============================

extern "C" void kernel_launch(void* const* d_in, const int* in_sizes, int n_in,
                              void* d_out, int out_size) {
    const float* x     = (const float*)d_in[0];
    const int*   erow  = (const int*)  d_in[1];
    const int*   ecol  = (const int*)  d_in[2];
    const float* eval  = (const float*)d_in[3];
    const float* W1    = (const float*)d_in[4];
    const float* b1    = (const float*)d_in[5];
    const float* W2    = (const float*)d_in[6];
    const float* b2    = (const float*)d_in[7];
    const float* alpha = (const float*)d_in[8];
    float* out = (float*)d_out;

    __half* suph = nullptr;
    float*  h1   = nullptr;
    cudaGetSymbolAddress((void**)&suph, g_sup_h);
    cudaGetSymbolAddress((void**)&h1, g_h1);

    // CSR build (used by both SpMM layers)
    zero_deg_kernel<<<(NNODES + 255) / 256, 256>>>();
    count_deg_kernel<<<NEDGES / 256, 256>>>(erow);
    scan1_kernel<<<NBLK_SCAN, SCAN_B>>>();
    scan2_kernel<<<1, 128>>>();
    scan3_kernel<<<NBLK_SCAN, SCAN_B>>>();
    scatter_kernel<<<NEDGES / 256, 256>>>(erow, ecol, eval);

    dim3 gemm_grid(NHID / 128, (NNODES + 127) / 128);

    // Layer 1
    gemm_mma_kernel<<<gemm_grid, 256>>>(NNODES, NHID, NFEAT, x, W1, suph);
    spmm_bias_prelu_kernel<<<NNODES / 4, 256>>>((const uint2*)suph, b1, alpha, (float4*)h1);

    // Layer 2
    gemm_mma_kernel<<<gemm_grid, 256>>>(NNODES, NHID, NHID, h1, W2, suph);
    spmm_bias_prelu_kernel<<<NNODES / 4, 256>>>((const uint2*)suph, b2, alpha, (float4*)out);
}